// round 7
// baseline (speedup 1.0000x reference)
#include <cuda_runtime.h>
#include <math_constants.h>

#define BS          32
#define NUM_GT      64
#define NUM_PRIORS  8400
#define NUM_CLASSES 80
#define TOPK        9

// output layout (float32, concat of returned tuple)
#define OFF_L 0
#define OFF_B (BS*NUM_PRIORS)                       // 268800
#define OFF_S (OFF_B + BS*NUM_PRIORS*4)             // 1344000
#define OFF_F (OFF_S + BS*NUM_PRIORS*NUM_CLASSES)   // 22848000

typedef unsigned long long u64;

// static zero-init; k_out resets nonzero entries so every graph replay sees zeros.
__device__ u64 g_claims[BS*NUM_PRIORS];   // bit g set => gt g claimed this prior

// One warp per (b, gt). Priors are a regular grid per level; the top-9 closest
// centers provably lie in the 5x5 index window around the nearest grid node
// (d9 <= 1.5*sqrt(2)*s < 2.5*s = min distance of any cell at offset >= 3).
// One window cell per lane; top-9 found by warp-wide rank (keys unique).
__global__ __launch_bounds__(128) void k_select(
    const float4* __restrict__ gt_bboxes,
    const float*  __restrict__ pad_flag)
{
  const int wgl  = blockIdx.x*4 + (threadIdx.x >> 5);  // 0..2047
  const int b    = wgl >> 6;
  const int g    = wgl & 63;
  const int lane = threadIdx.x & 31;

  const float4 G = __ldg(&gt_bboxes[b*NUM_GT + g]);
  const float gcx = (G.x + G.z)*0.5f, gcy = (G.y + G.w)*0.5f;
  const float garea = (G.z - G.x)*(G.w - G.y);

  const int  qy = lane / 5;                 // 0..6 (lanes 25..31 invalid)
  const int  dxi = lane - qy*5 - 2;         // -2..2
  const int  dyi = qy - 2;
  const bool lane_ok = lane < 25;

  const int   Cn [3] = {80, 40, 20};
  const float Cs [3] = {8.f, 16.f, 32.f};
  const float Cis[3] = {0.125f, 0.0625f, 0.03125f};
  const int   Cst[3] = {0, 6400, 8000};

  float ov[3]; bool win[3]; float pxv[3], pyv[3]; int pidxv[3];
  float osum = 0.f;

  #pragma unroll
  for (int l = 0; l < 3; l++) {
    const int n = Cn[l]; const float s = Cs[l];
    const int jx0 = (int)floorf(gcx * Cis[l]);   // exact (power-of-two scale)
    const int jy0 = (int)floorf(gcy * Cis[l]);
    const int jx = jx0 + dxi, jy = jy0 + dyi;
    const bool v = lane_ok && (unsigned)jx < (unsigned)n && (unsigned)jy < (unsigned)n;

    const float px = ((float)jx + 0.5f) * s;     // == reference center, exact
    const float py = ((float)jy + 0.5f) * s;
    const float dx = gcx - px, dy = gcy - py;
    const float d  = fmaf(dx, dx, dy*dy);
    const int   pidx = Cst[l] + jy*n + jx;
    const u64 key = v ? (((u64)__float_as_uint(d) << 32) | (unsigned)pidx) : ~0ull;

    // rank = #keys strictly less (keys unique among valid lanes)
    int r = 0;
    #pragma unroll
    for (int src = 0; src < 25; src++) {
      u64 a = __shfl_sync(0xffffffffu, key, src);
      r += (a < key);
    }
    const bool w = v && (r < TOPK);   // >=16 valid cells always, so exactly 9 win
    win[l] = w; pxv[l] = px; pyv[l] = py; pidxv[l] = pidx;

    // candidate overlap (gt vs 5*stride cell), union clamped to 1e-6
    float o = 0.f;
    if (w) {
      const float h = 2.5f*s;
      const float x1 = px - h, x2 = px + h, y1 = py - h, y2 = py + h;
      float iw = fmaxf(fminf(G.z, x2) - fmaxf(G.x, x1), 0.f);
      float ih = fmaxf(fminf(G.w, y2) - fmaxf(G.y, y1), 0.f);
      float inter = iw*ih;
      float pa = (x2 - x1)*(y2 - y1);
      o = inter / fmaxf(garea + pa - inter, 1e-6f);
    }
    ov[l] = o;
    osum += o;
  }

  // thr = mean + std(ddof=1) over the 27 winner overlaps
  float ssum = osum;
  #pragma unroll
  for (int off = 16; off; off >>= 1) ssum += __shfl_xor_sync(0xffffffffu, ssum, off);
  const float mean = ssum / 27.f;
  float vsum = 0.f;
  #pragma unroll
  for (int l = 0; l < 3; l++)
    if (win[l]) { float e = ov[l] - mean; vsum = fmaf(e, e, vsum); }
  #pragma unroll
  for (int off = 16; off; off >>= 1) vsum += __shfl_xor_sync(0xffffffffu, vsum, off);
  const float thr = mean + sqrtf(vsum / 26.f);

  const bool pad = __ldg(&pad_flag[b*NUM_GT + g]) > 0.f;
  #pragma unroll
  for (int l = 0; l < 3; l++) {
    if (win[l] && pad && ov[l] > thr) {
      float m = fminf(fminf(pxv[l] - G.x, pyv[l] - G.y),
                      fminf(G.z - pxv[l], G.w - pyv[l]));
      if (m > 1e-9f)   // prior center strictly inside gt
        atomicOr(&g_claims[b*NUM_PRIORS + pidxv[l]], 1ull << g);
    }
  }
}

// analytic prior cell box from flat prior index
__device__ __forceinline__ float4 cell_box(int p) {
  int l = (p < 6400) ? 0 : (p < 8000 ? 1 : 2);
  int n = (l == 0) ? 80 : (l == 1 ? 40 : 20);
  float s = (l == 0) ? 8.f : (l == 1 ? 16.f : 32.f);
  int st = (l == 0) ? 0 : (l == 1 ? 6400 : 8000);
  int rel = p - st;
  int jy = rel / n, jx = rel - jy*n;
  float px = ((float)jx + 0.5f)*s, py = ((float)jy + 0.5f)*s;
  float h = 2.5f*s;
  return make_float4(px - h, py - h, px + h, py + h);
}

#define OT     256                       // threads per block
#define NCHUNK (BS*NUM_PRIORS/OT)        // 1050 chunks of 256 keys
#define NBLK   (NCHUNK/2)                // 525 blocks, 2 distant chunks each

// Warp-autonomous resolve + streaming stores (exact R5 body), executed for one
// 256-key chunk. Kept as a separate function; called twice sequentially.
__device__ __forceinline__ void out_chunk(
    int key, u64 m,
    const float4* __restrict__ gt_bboxes,
    const int*    __restrict__ gt_labels,
    const float4* __restrict__ pred,
    float* __restrict__ out, int lane)
{
  const int fg = __popcll(m);
  const int pb = key / NUM_PRIORS;

  int gi = 0;
  if (fg == 1) {
    gi = __ffsll((long long)m) - 1;
  } else if (fg > 1) {
    // resolve multi-claimed prior: first-max over ALL gts of gt-vs-cell IoU
    float4 cb = cell_box(key - pb*NUM_PRIORS);
    float pa = (cb.z - cb.x)*(cb.w - cb.y);
    float best = -1.f;
    for (int gg = 0; gg < NUM_GT; gg++) {
      float4 T = __ldg(&gt_bboxes[pb*NUM_GT + gg]);
      float iw = fmaxf(fminf(T.z, cb.z) - fmaxf(T.x, cb.x), 0.f);
      float ih = fmaxf(fminf(T.w, cb.w) - fmaxf(T.y, cb.y), 0.f);
      float inter = iw*ih;
      float ga = (T.z - T.x)*(T.w - T.y);
      float ovl = inter / fmaxf(ga + pa - inter, 1e-6f);
      if (ovl > best) { best = ovl; gi = gg; }
    }
  }

  const float4 T = __ldg(&gt_bboxes[pb*NUM_GT + gi]);
  float labelv, fgm; int col = -1; float val = 0.f;
  if (fg > 0) {
    int lab = __ldg(&gt_labels[pb*NUM_GT + gi]);
    labelv = (float)lab; col = lab; fgm = 1.f;
    // score weight = IoU(gt, pred), union + 1e-9
    float4 P = __ldg(&pred[key]);
    float iw = fmaxf(fminf(T.z, P.z) - fmaxf(T.x, P.x), 0.f);
    float ih = fmaxf(fminf(T.w, P.w) - fmaxf(T.y, P.y), 0.f);
    float inter = iw*ih;
    float ga = (T.z - T.x)*(T.w - T.y);
    float pa = (P.z - P.x)*(P.w - P.y);
    val = inter / (ga + pa - inter + 1e-9f);
  } else {
    labelv = (float)NUM_CLASSES; fgm = 0.f;   // background; bbox = gt[pb][0]
  }

  __stcs(&out[OFF_L + key], labelv);
  __stcs((float4*)out + (OFF_B >> 2) + key, T);
  __stcs(&out[OFF_F + key], fgm);

  // score slab: warp owns priors [keyw, keyw+32) => 640 contiguous float4s
  const int keyw = key & ~31;
  float4* sco = (float4*)out + (OFF_S >> 2) + (size_t)keyw*(NUM_CLASSES/4);
  #pragma unroll
  for (int k = 0; k < 20; k++) {
    const int i  = lane + 32*k;
    const int lp = i / 20;
    const int c0 = (i - lp*20) * 4;
    const int   cl = __shfl_sync(0xffffffffu, col, lp);
    const float vv = __shfl_sync(0xffffffffu, val, lp);
    float4 rr;
    rr.x = (cl == c0    ) ? vv : 0.f;
    rr.y = (cl == c0 + 1) ? vv : 0.f;
    rr.z = (cl == c0 + 2) ? vv : 0.f;
    rr.w = (cl == c0 + 3) ? vv : 0.f;
    __stcs(&sco[i], rr);
  }
}

__global__ __launch_bounds__(OT, 6) void k_out(
    const float4* __restrict__ gt_bboxes,
    const int*    __restrict__ gt_labels,
    const float4* __restrict__ pred,
    float* __restrict__ out)
{
  const int tid  = threadIdx.x;
  const int lane = tid & 31;
  const int k0 = blockIdx.x        *OT + tid;   // chunk A
  const int k1 = (blockIdx.x + NBLK)*OT + tid;  // chunk B (distant: variance averaging)

  // issue both claim loads up front; chunk B's latency hides under chunk A
  u64 m0 = g_claims[k0];
  u64 m1 = g_claims[k1];
  if (m0) g_claims[k0] = 0;   // reset for next graph replay
  if (m1) g_claims[k1] = 0;

  out_chunk(k0, m0, gt_bboxes, gt_labels, pred, out, lane);
  out_chunk(k1, m1, gt_bboxes, gt_labels, pred, out, lane);
}

extern "C" void kernel_launch(void* const* d_in, const int* in_sizes, int n_in,
                              void* d_out, int out_size)
{
  const float4* pred = (const float4*)d_in[0];
  const int*    gtl  = (const int*)d_in[2];
  const float4* gtb  = (const float4*)d_in[3];
  const float*  pad  = (const float*)d_in[4];
  float* out = (float*)d_out;

  k_select<<<BS*NUM_GT/4, 128>>>(gtb, pad);
  k_out   <<<NBLK, OT>>>(gtb, gtl, pred, out);
}

// round 8
// speedup vs baseline: 3.2226x; 3.2226x over previous
#include <cuda_runtime.h>
#include <math_constants.h>

#define BS          32
#define NUM_GT      64
#define NUM_PRIORS  8400
#define NUM_CLASSES 80
#define TOPK        9

// output layout (float32, concat of returned tuple)
#define OFF_L 0
#define OFF_B (BS*NUM_PRIORS)                       // 268800
#define OFF_S (OFF_B + BS*NUM_PRIORS*4)             // 1344000
#define OFF_F (OFF_S + BS*NUM_PRIORS*NUM_CLASSES)   // 22848000

typedef unsigned long long u64;

// static zero-init; k_out resets nonzero entries so every graph replay sees zeros.
__device__ u64 g_claims[BS*NUM_PRIORS];   // bit g set => gt g claimed this prior

// One warp per (b, gt). Priors are a regular grid per level; the top-9 closest
// centers provably lie in the 5x5 index window around the nearest grid node
// (d9 <= 1.5*sqrt(2)*s < 2.5*s = min distance of any cell at offset >= 3).
// One window cell per lane; top-9 found by warp-wide rank (keys unique).
__global__ __launch_bounds__(128) void k_select(
    const float4* __restrict__ gt_bboxes,
    const float*  __restrict__ pad_flag)
{
  const int wgl  = blockIdx.x*4 + (threadIdx.x >> 5);  // 0..2047
  const int b    = wgl >> 6;
  const int g    = wgl & 63;
  const int lane = threadIdx.x & 31;

  const float4 G = __ldg(&gt_bboxes[b*NUM_GT + g]);
  const float gcx = (G.x + G.z)*0.5f, gcy = (G.y + G.w)*0.5f;
  const float garea = (G.z - G.x)*(G.w - G.y);

  const int  qy = lane / 5;                 // 0..6 (lanes 25..31 invalid)
  const int  dxi = lane - qy*5 - 2;         // -2..2
  const int  dyi = qy - 2;
  const bool lane_ok = lane < 25;

  const int   Cn [3] = {80, 40, 20};
  const float Cs [3] = {8.f, 16.f, 32.f};
  const float Cis[3] = {0.125f, 0.0625f, 0.03125f};
  const int   Cst[3] = {0, 6400, 8000};

  float ov[3]; bool win[3]; float pxv[3], pyv[3]; int pidxv[3];
  float osum = 0.f;

  #pragma unroll
  for (int l = 0; l < 3; l++) {
    const int n = Cn[l]; const float s = Cs[l];
    const int jx0 = (int)floorf(gcx * Cis[l]);   // exact (power-of-two scale)
    const int jy0 = (int)floorf(gcy * Cis[l]);
    const int jx = jx0 + dxi, jy = jy0 + dyi;
    const bool v = lane_ok && (unsigned)jx < (unsigned)n && (unsigned)jy < (unsigned)n;

    const float px = ((float)jx + 0.5f) * s;     // == reference center, exact
    const float py = ((float)jy + 0.5f) * s;
    const float dx = gcx - px, dy = gcy - py;
    const float d  = fmaf(dx, dx, dy*dy);
    const int   pidx = Cst[l] + jy*n + jx;
    const u64 key = v ? (((u64)__float_as_uint(d) << 32) | (unsigned)pidx) : ~0ull;

    // rank = #keys strictly less (keys unique among valid lanes)
    int r = 0;
    #pragma unroll
    for (int src = 0; src < 25; src++) {
      u64 a = __shfl_sync(0xffffffffu, key, src);
      r += (a < key);
    }
    const bool w = v && (r < TOPK);   // >=16 valid cells always, so exactly 9 win
    win[l] = w; pxv[l] = px; pyv[l] = py; pidxv[l] = pidx;

    // candidate overlap (gt vs 5*stride cell), union clamped to 1e-6
    float o = 0.f;
    if (w) {
      const float h = 2.5f*s;
      const float x1 = px - h, x2 = px + h, y1 = py - h, y2 = py + h;
      float iw = fmaxf(fminf(G.z, x2) - fmaxf(G.x, x1), 0.f);
      float ih = fmaxf(fminf(G.w, y2) - fmaxf(G.y, y1), 0.f);
      float inter = iw*ih;
      float pa = (x2 - x1)*(y2 - y1);
      o = inter / fmaxf(garea + pa - inter, 1e-6f);
    }
    ov[l] = o;
    osum += o;
  }

  // thr = mean + std(ddof=1) over the 27 winner overlaps
  float ssum = osum;
  #pragma unroll
  for (int off = 16; off; off >>= 1) ssum += __shfl_xor_sync(0xffffffffu, ssum, off);
  const float mean = ssum / 27.f;
  float vsum = 0.f;
  #pragma unroll
  for (int l = 0; l < 3; l++)
    if (win[l]) { float e = ov[l] - mean; vsum = fmaf(e, e, vsum); }
  #pragma unroll
  for (int off = 16; off; off >>= 1) vsum += __shfl_xor_sync(0xffffffffu, vsum, off);
  const float thr = mean + sqrtf(vsum / 26.f);

  const bool pad = __ldg(&pad_flag[b*NUM_GT + g]) > 0.f;
  #pragma unroll
  for (int l = 0; l < 3; l++) {
    if (win[l] && pad && ov[l] > thr) {
      float m = fminf(fminf(pxv[l] - G.x, pyv[l] - G.y),
                      fminf(G.z - pxv[l], G.w - pyv[l]));
      if (m > 1e-9f)   // prior center strictly inside gt
        atomicOr(&g_claims[b*NUM_PRIORS + pidxv[l]], 1ull << g);
    }
  }
}

// analytic prior cell box from flat prior index
__device__ __forceinline__ float4 cell_box(int p) {
  int l = (p < 6400) ? 0 : (p < 8000 ? 1 : 2);
  int n = (l == 0) ? 80 : (l == 1 ? 40 : 20);
  float s = (l == 0) ? 8.f : (l == 1 ? 16.f : 32.f);
  int st = (l == 0) ? 0 : (l == 1 ? 6400 : 8000);
  int rel = p - st;
  int jy = rel / n, jx = rel - jy*n;
  float px = ((float)jx + 0.5f)*s, py = ((float)jy + 0.5f)*s;
  float h = 2.5f*s;
  return make_float4(px - h, py - h, px + h, py + h);
}

__device__ __forceinline__ float cell_iou(float4 T, float4 cb, float pa) {
  float iw = fmaxf(fminf(T.z, cb.z) - fmaxf(T.x, cb.x), 0.f);
  float ih = fmaxf(fminf(T.w, cb.w) - fmaxf(T.y, cb.y), 0.f);
  float inter = iw*ih;
  float ga = (T.z - T.x)*(T.w - T.y);
  return inter / fmaxf(ga + pa - inter, 1e-6f);
}

#define OT 256

// Warp-autonomous: no smem, no block sync. One thread = one prior.
// fg>1 lanes resolved warp-cooperatively (2 gts per lane + warp argmax).
__global__ __launch_bounds__(OT) void k_out(
    const float4* __restrict__ gt_bboxes,
    const int*    __restrict__ gt_labels,
    const float4* __restrict__ pred,
    float* __restrict__ out)
{
  const int key  = blockIdx.x*OT + threadIdx.x;   // flat b*NUM_PRIORS+p
  const int lane = threadIdx.x & 31;

  u64 m = g_claims[key];
  if (m) g_claims[key] = 0;        // reset for next graph replay
  const int fg = __popcll(m);
  const int pb = key / NUM_PRIORS;

  int gi = (fg >= 1) ? (__ffsll((long long)m) - 1) : 0;

  // warp-cooperative first-max argmax over ALL 64 gts for fg>1 lanes
  unsigned need = __ballot_sync(0xffffffffu, fg > 1);
  while (need) {
    const int leader = __ffs(need) - 1; need &= need - 1;
    const int lkey = (key & ~31) | leader;        // same warp, same chunk
    const int lpb  = lkey / NUM_PRIORS;
    const float4 cb = cell_box(lkey - lpb*NUM_PRIORS);
    const float  pa = (cb.z - cb.x)*(cb.w - cb.y);
    // lane evaluates gt=lane and gt=lane+32 (first-max: lower index wins ties)
    float4 T0 = __ldg(&gt_bboxes[lpb*NUM_GT + lane]);
    float4 T1 = __ldg(&gt_bboxes[lpb*NUM_GT + lane + 32]);
    float o0 = cell_iou(T0, cb, pa);
    float o1 = cell_iou(T1, cb, pa);
    float bv = o0; int bi = lane;
    if (o1 > bv) { bv = o1; bi = lane + 32; }
    #pragma unroll
    for (int off = 16; off; off >>= 1) {
      float ovx = __shfl_xor_sync(0xffffffffu, bv, off);
      int   oix = __shfl_xor_sync(0xffffffffu, bi, off);
      if (ovx > bv || (ovx == bv && oix < bi)) { bv = ovx; bi = oix; }
    }
    if (lane == leader) gi = bi;
  }

  const float4 T = __ldg(&gt_bboxes[pb*NUM_GT + gi]);
  float labelv, fgm; int col = -1; float val = 0.f;
  if (fg > 0) {
    int lab = __ldg(&gt_labels[pb*NUM_GT + gi]);
    labelv = (float)lab; col = lab; fgm = 1.f;
    // score weight = IoU(gt, pred), union + 1e-9
    float4 P = __ldg(&pred[key]);
    float iw = fmaxf(fminf(T.z, P.z) - fmaxf(T.x, P.x), 0.f);
    float ih = fmaxf(fminf(T.w, P.w) - fmaxf(T.y, P.y), 0.f);
    float inter = iw*ih;
    float ga = (T.z - T.x)*(T.w - T.y);
    float pa = (P.z - P.x)*(P.w - P.y);
    val = inter / (ga + pa - inter + 1e-9f);
  } else {
    labelv = (float)NUM_CLASSES; fgm = 0.f;   // background; bbox = gt[pb][0]
  }

  __stcs(&out[OFF_L + key], labelv);
  __stcs((float4*)out + (OFF_B >> 2) + key, T);
  __stcs(&out[OFF_F + key], fgm);

  // score slab: warp owns priors [keyw, keyw+32) => 640 contiguous float4s
  const int keyw = key & ~31;
  float4* sco = (float4*)out + (OFF_S >> 2) + (size_t)keyw*(NUM_CLASSES/4);
  #pragma unroll
  for (int k = 0; k < 20; k++) {
    const int i  = lane + 32*k;
    const int lp = i / 20;
    const int c0 = (i - lp*20) * 4;
    const int   cl = __shfl_sync(0xffffffffu, col, lp);
    const float vv = __shfl_sync(0xffffffffu, val, lp);
    float4 rr;
    rr.x = (cl == c0    ) ? vv : 0.f;
    rr.y = (cl == c0 + 1) ? vv : 0.f;
    rr.z = (cl == c0 + 2) ? vv : 0.f;
    rr.w = (cl == c0 + 3) ? vv : 0.f;
    __stcs(&sco[i], rr);
  }
}

extern "C" void kernel_launch(void* const* d_in, const int* in_sizes, int n_in,
                              void* d_out, int out_size)
{
  const float4* pred = (const float4*)d_in[0];
  const int*    gtl  = (const int*)d_in[2];
  const float4* gtb  = (const float4*)d_in[3];
  const float*  pad  = (const float*)d_in[4];
  float* out = (float*)d_out;

  k_select<<<BS*NUM_GT/4, 128>>>(gtb, pad);
  k_out   <<<BS*NUM_PRIORS/OT, OT>>>(gtb, gtl, pred, out);
}